// round 5
// baseline (speedup 1.0000x reference)
#include <cuda_runtime.h>

// MultinomialModule via summation swap, fully fused into ONE persistent kernel.
//   sum_j searchsorted(cdf,u_j,right) = sum_i ( M - #{u_j < cdf[i]} )
//   #{u < v} = U[floor(v*K)] + H[floor(v*K)] * frac(v*K)
// H = histogram of u over K=2^20 bins; U = exclusive prefix of H.
// Clip idx to N-1  <=>  skip the i = N-1 term. Correction quantized to 1/65536.
//
// Phases inside one kernel, separated by software grid barriers (all blocks
// provably co-resident via __launch_bounds__(256,4), grid = 148*4 = 592):
//   P0 zero H, g_acc | P1 histogram | P2 tile sums (H int + x float)
//   P3 scans of tile sums (blocks 0/1) | P4 pack UH = {prefix,count}
//   P5 gather + accumulate | P6 finalize

#define TILE    1024
#define NT_MAX  1024
#define KBITS   20
#define KTAB    (1 << KBITS)
#define GRID    592
#define BLOCK   256
#define NTHREADS (GRID * BLOCK)

__device__ int   g_H[KTAB];
__device__ int2  g_UH[KTAB];
__device__ int   g_hsum[NT_MAX];
__device__ int   g_hoff[NT_MAX];
__device__ float g_xsum[NT_MAX];
__device__ float g_xoff[NT_MAX];
__device__ float g_inv_total;
__device__ unsigned long long g_acc;
__device__ unsigned g_count;   // zero-init
__device__ unsigned g_gen;     // zero-init, monotone across replays

__device__ __forceinline__ void grid_barrier() {
    __syncthreads();
    if (threadIdx.x == 0) {
        __threadfence();
        unsigned gen = *(volatile unsigned*)&g_gen;   // pre-release value
        if (atomicAdd(&g_count, 1u) == GRID - 1) {
            g_count = 0;
            __threadfence();
            atomicAdd(&g_gen, 1u);                    // release
        } else {
            while (*(volatile unsigned*)&g_gen == gen) __nanosleep(32);
        }
        __threadfence();
    }
    __syncthreads();
}

__device__ __forceinline__ void hbump(float v) {
    unsigned b = (unsigned)(v * (float)KTAB);         // exact *2^20
    if (b >= KTAB) b = KTAB - 1;
    atomicAdd(&g_H[b], 1);
}

__global__ void __launch_bounds__(BLOCK, 4)
k_fused(const float* __restrict__ x, const float* __restrict__ u,
        float* __restrict__ out, int N, int M, int ntiles) {
    int t = threadIdx.x;
    int lane = t & 31, w = t >> 5;
    int gtid = blockIdx.x * BLOCK + t;

    // ---- P0: zero histogram + accumulator ----
    for (int i = gtid; i < KTAB / 4; i += NTHREADS)
        reinterpret_cast<int4*>(g_H)[i] = make_int4(0, 0, 0, 0);
    if (gtid == 0) g_acc = 0ull;
    grid_barrier();

    // ---- P1: histogram of u ----
    for (int j0 = gtid * 4; j0 < M; j0 += NTHREADS * 4) {
        if (j0 + 3 < M) {
            float4 v = *reinterpret_cast<const float4*>(u + j0);
            hbump(v.x); hbump(v.y); hbump(v.z); hbump(v.w);
        } else {
            for (int k = 0; k < 4; k++) if (j0 + k < M) hbump(u[j0 + k]);
        }
    }
    grid_barrier();

    // ---- P2: tile sums (H tiles 0..1023 int, x tiles NT_MAX.. float) ----
    {
        __shared__ int   wsi[8];
        __shared__ float wsf[8];
        for (int b = blockIdx.x; b < NT_MAX + ntiles; b += GRID) {
            if (b < NT_MAX) {
                int i0 = b * TILE + t * 4;
                int4 h = *reinterpret_cast<const int4*>(g_H + i0);
                int s = h.x + h.y + h.z + h.w;
                #pragma unroll
                for (int off = 16; off; off >>= 1) s += __shfl_down_sync(0xffffffffu, s, off);
                if (lane == 0) wsi[w] = s;
                __syncthreads();
                if (t < 8) {
                    int v = wsi[t];
                    #pragma unroll
                    for (int off = 4; off; off >>= 1) v += __shfl_down_sync(0xffu, v, off);
                    if (t == 0) g_hsum[b] = v;
                }
            } else {
                int tile = b - NT_MAX;
                int i0 = tile * TILE + t * 4;
                float s = 0.f;
                if (i0 + 3 < N) {
                    float4 v = *reinterpret_cast<const float4*>(x + i0);
                    s = ((v.x + v.y) + v.z) + v.w;
                } else {
                    #pragma unroll
                    for (int k = 0; k < 4; k++) if (i0 + k < N) s += x[i0 + k];
                }
                #pragma unroll
                for (int off = 16; off; off >>= 1) s += __shfl_down_sync(0xffffffffu, s, off);
                if (lane == 0) wsf[w] = s;
                __syncthreads();
                if (t < 8) {
                    float v = wsf[t];
                    #pragma unroll
                    for (int off = 4; off; off >>= 1) v += __shfl_down_sync(0xffu, v, off);
                    if (t == 0) g_xsum[tile] = v;
                }
            }
            __syncthreads();   // protect wsi/wsf reuse
        }
    }
    grid_barrier();

    // ---- P3: scans of the tile-sum arrays (block 0 int, block 1 float) ----
    if (blockIdx.x == 0) {
        int4 h = reinterpret_cast<const int4*>(g_hsum)[t];     // 4 entries/thread
        int ts = h.x + h.y + h.z + h.w;
        int sc = ts;
        #pragma unroll
        for (int off = 1; off < 32; off <<= 1) {
            int n = __shfl_up_sync(0xffffffffu, sc, off);
            if (lane >= off) sc += n;
        }
        __shared__ int wt[8], wo[8];
        if (lane == 31) wt[w] = sc;
        __syncthreads();
        if (t < 8) {
            int wv = wt[t], ws = wv;
            #pragma unroll
            for (int off = 1; off < 8; off <<= 1) {
                int n = __shfl_up_sync(0xffu, ws, off);
                if (t >= off) ws += n;
            }
            wo[t] = ws - wv;
        }
        __syncthreads();
        int base = (sc - ts) + wo[w];
        int4 o;
        o.x = base; o.y = base + h.x; o.z = o.y + h.y; o.w = o.z + h.z;
        reinterpret_cast<int4*>(g_hoff)[t] = o;
    } else if (blockIdx.x == 1) {
        float v[4];
        #pragma unroll
        for (int k = 0; k < 4; k++) {
            int i = t * 4 + k;
            v[k] = (i < ntiles) ? g_xsum[i] : 0.f;
        }
        float ts = ((v[0] + v[1]) + v[2]) + v[3];
        float sc = ts;
        #pragma unroll
        for (int off = 1; off < 32; off <<= 1) {
            float n = __shfl_up_sync(0xffffffffu, sc, off);
            if (lane >= off) sc += n;
        }
        __shared__ float wtf[8], wof[8], sh_total;
        if (lane == 31) wtf[w] = sc;
        __syncthreads();
        if (t < 8) {
            float wv = wtf[t], ws = wv;
            #pragma unroll
            for (int off = 1; off < 8; off <<= 1) {
                float n = __shfl_up_sync(0xffu, ws, off);
                if (t >= off) ws += n;
            }
            wof[t] = ws - wv;
            if (t == 7) sh_total = ws;
        }
        __syncthreads();
        if (t == 0) g_inv_total = 1.0f / sh_total;
        float base = (sc - ts) + wof[w];
        float acc = base;
        #pragma unroll
        for (int k = 0; k < 4; k++) {
            int i = t * 4 + k;
            if (i < ntiles) g_xoff[i] = acc;
            acc += v[k];
        }
    }
    grid_barrier();

    // ---- P4: materialize UH = {exclusive prefix, count} per bin ----
    {
        __shared__ int wt4[8], wo4[8];
        for (int tile = blockIdx.x; tile < NT_MAX; tile += GRID) {
            int i0 = tile * TILE + t * 4;
            int4 h = *reinterpret_cast<const int4*>(g_H + i0);
            int s = h.x + h.y + h.z + h.w;
            int sc = s;
            #pragma unroll
            for (int off = 1; off < 32; off <<= 1) {
                int n = __shfl_up_sync(0xffffffffu, sc, off);
                if (lane >= off) sc += n;
            }
            if (lane == 31) wt4[w] = sc;
            __syncthreads();
            if (t < 8) {
                int wv = wt4[t], ws = wv;
                #pragma unroll
                for (int off = 1; off < 8; off <<= 1) {
                    int n = __shfl_up_sync(0xffu, ws, off);
                    if (t >= off) ws += n;
                }
                wo4[t] = ws - wv;
            }
            __syncthreads();
            int base = g_hoff[tile] + (sc - s) + wo4[w];
            int4 p0, p1;
            p0.x = base;            p0.y = h.x;
            p0.z = base + h.x;      p0.w = h.y;
            p1.x = p0.z + h.y;      p1.y = h.z;
            p1.z = p1.x + h.z;      p1.w = h.w;
            reinterpret_cast<int4*>(&g_UH[i0])[0] = p0;
            reinterpret_cast<int4*>(&g_UH[i0])[1] = p1;
            __syncthreads();   // protect wt4/wo4 reuse
        }
    }
    grid_barrier();

    // ---- P5: x scan in registers -> gather UH -> accumulate ----
    {
        __shared__ float wt5[8], wo5[8];
        long long local = 0;
        float inv = g_inv_total;
        for (int tile = blockIdx.x; tile < ntiles; tile += GRID) {
            int i0 = tile * TILE + t * 4;
            float v[4];
            bool full = (i0 + 3 < N);
            if (full) {
                float4 f = *reinterpret_cast<const float4*>(x + i0);
                v[0] = f.x; v[1] = f.y; v[2] = f.z; v[3] = f.w;
            } else {
                #pragma unroll
                for (int k = 0; k < 4; k++) v[k] = (i0 + k < N) ? x[i0 + k] : 0.f;
            }
            float s = ((v[0] + v[1]) + v[2]) + v[3];
            float sc = s;
            #pragma unroll
            for (int off = 1; off < 32; off <<= 1) {
                float n = __shfl_up_sync(0xffffffffu, sc, off);
                if (lane >= off) sc += n;
            }
            if (lane == 31) wt5[w] = sc;
            __syncthreads();
            if (t < 8) {
                float wv = wt5[t], ws = wv;
                #pragma unroll
                for (int off = 1; off < 8; off <<= 1) {
                    float n = __shfl_up_sync(0xffu, ws, off);
                    if (t >= off) ws += n;
                }
                wo5[t] = ws - wv;
            }
            __syncthreads();
            float acc = g_xoff[tile] + (sc - s) + wo5[w];
            #pragma unroll
            for (int e = 0; e < 4; e++) {
                int i = i0 + e;
                acc += v[e];
                if (i < N && i != N - 1) {            // skip last term == clip to N-1
                    float ck = (acc * inv) * (float)KTAB;
                    int k = (int)ck;
                    if (k > KTAB - 1) k = KTAB - 1;
                    if (k < 0) k = 0;
                    float frac = ck - (float)k;
                    if (frac < 0.f) frac = 0.f;
                    if (frac > 1.f) frac = 1.f;
                    int2 uh = __ldg(&g_UH[k]);
                    long long ip = ((long long)(M - uh.x)) << 16;
                    int q = (int)(frac * (float)uh.y * 65536.0f);
                    local += ip - (long long)q;
                }
            }
            __syncthreads();   // protect wt5/wo5 reuse
        }
        // block reduce + one atomic
        #pragma unroll
        for (int off = 16; off; off >>= 1)
            local += __shfl_down_sync(0xffffffffu, local, off);
        __shared__ long long ws8[8];
        if (lane == 0) ws8[w] = local;
        __syncthreads();
        if (t < 8) {
            long long vv = ws8[t];
            #pragma unroll
            for (int off = 4; off; off >>= 1)
                vv += __shfl_down_sync(0xffu, vv, off);
            if (t == 0 && vv != 0) atomicAdd(&g_acc, (unsigned long long)vv);
        }
    }
    grid_barrier();

    // ---- P6: finalize ----
    if (gtid == 0)
        out[0] = (float)((double)g_acc / (65536.0 * (double)M));
}

extern "C" void kernel_launch(void* const* d_in, const int* in_sizes, int n_in,
                              void* d_out, int out_size) {
    const float* x = (const float*)d_in[0];
    const float* u = (const float*)d_in[1];
    float* out = (float*)d_out;
    int N = in_sizes[0];
    int M = in_sizes[1];
    int ntiles = (N + TILE - 1) / TILE;
    k_fused<<<GRID, BLOCK>>>(x, u, out, N, M, ntiles);
}

// round 6
// speedup vs baseline: 1.7068x; 1.7068x over previous
#include <cuda_runtime.h>

// MultinomialModule via summation swap, 3 launches:
//   sum_j searchsorted(cdf,u_j,right) = sum_i ( M - #{u_j < cdf[i]} )
//   #{u < v} = U[floor(v*K)] + H[floor(v*K)] * frac(v*K)
// H = histogram of u over K=2^20 bins. U split as U[k] = hoff[k>>10] + local[k],
// where hoff (1024 tile offsets) is re-derived cheaply per block in L3 shared mem.
// Clip idx to N-1  <=>  skip the i = N-1 term. Correction quantized to 1/65536.
//
//   L1 k_pre    : u histogram (blocks [0,HB)) || x tile sums (blocks [HB,..))
//   L2 k_mid    : per-tile local prefix -> UH{local,count}, g_hsum, re-zero H;
//                 block HT scans x tile sums -> g_xoff, g_inv_total
//   L3 k_gather : block-scan g_hsum into smem; x scan -> gather UH -> accumulate;
//                 last block finalizes out and resets state (replay-safe)

#define TILE    1024
#define NT_MAX  1024
#define KBITS   20
#define KTAB    (1 << KBITS)
#define HT      (KTAB / TILE)          // 1024 histogram tiles

__device__ int   g_H[KTAB];            // zero-init; re-zeroed by k_mid each run
__device__ int2  g_UH[KTAB];           // {local prefix within tile, count}
__device__ int   g_hsum[HT];           // per-H-tile totals
__device__ float g_xsum[NT_MAX];
__device__ float g_xoff[NT_MAX];
__device__ float g_inv_total;
__device__ unsigned long long g_acc;   // zero-init; reset by finalize
__device__ unsigned g_xdone;           // zero-init; reset by finalize

__device__ __forceinline__ void hbump(float v) {
    unsigned b = (unsigned)(v * (float)KTAB);        // exact *2^20
    if (b >= KTAB) b = KTAB - 1;
    atomicAdd(&g_H[b], 1);
}

// ---- L1: histogram of u (blocks [0,HB)) + x tile sums (blocks [HB, HB+xnt)) ----
__global__ void k_pre(const float* __restrict__ u, const float* __restrict__ x,
                      int N, int M, int HB) {
    int b = blockIdx.x;
    int t = threadIdx.x;
    if (b < HB) {
        int j0 = (b * blockDim.x + t) * 4;
        if (j0 + 3 < M) {
            float4 v = *reinterpret_cast<const float4*>(u + j0);
            hbump(v.x); hbump(v.y); hbump(v.z); hbump(v.w);
        } else {
            for (int k = 0; k < 4; k++) if (j0 + k < M) hbump(u[j0 + k]);
        }
    } else {
        int tile = b - HB;
        int i0 = tile * TILE + t * 4;
        float s = 0.f;
        if (i0 + 3 < N) {
            float4 v = *reinterpret_cast<const float4*>(x + i0);
            s = ((v.x + v.y) + v.z) + v.w;
        } else {
            #pragma unroll
            for (int k = 0; k < 4; k++) if (i0 + k < N) s += x[i0 + k];
        }
        #pragma unroll
        for (int off = 16; off; off >>= 1) s += __shfl_down_sync(0xffffffffu, s, off);
        __shared__ float wsf[8];
        if ((t & 31) == 0) wsf[t >> 5] = s;
        __syncthreads();
        if (t < 8) {
            float v = wsf[t];
            #pragma unroll
            for (int off = 4; off; off >>= 1) v += __shfl_down_sync(0xffu, v, off);
            if (t == 0) g_xsum[tile] = v;
        }
    }
}

// ---- L2: per-H-tile local prefix + totals + H re-zero; x scan in block HT ----
__global__ void k_mid(int xnt) {
    int t = threadIdx.x, lane = t & 31, w = t >> 5;
    if (blockIdx.x < HT) {
        int tile = blockIdx.x;
        int i0 = tile * TILE + t * 4;
        int4 h = *reinterpret_cast<const int4*>(g_H + i0);
        int s = h.x + h.y + h.z + h.w;
        int sc = s;
        #pragma unroll
        for (int off = 1; off < 32; off <<= 1) {
            int n = __shfl_up_sync(0xffffffffu, sc, off);
            if (lane >= off) sc += n;
        }
        __shared__ int wt[8], wo[8];
        if (lane == 31) wt[w] = sc;
        __syncthreads();
        if (t < 8) {
            int wv = wt[t], ws = wv;
            #pragma unroll
            for (int off = 1; off < 8; off <<= 1) {
                int n = __shfl_up_sync(0xffu, ws, off);
                if (t >= off) ws += n;
            }
            wo[t] = ws - wv;
            if (t == 7) g_hsum[tile] = ws;           // block total
        }
        __syncthreads();
        int base = (sc - s) + wo[w];                 // local exclusive prefix
        int4 p0, p1;
        p0.x = base;        p0.y = h.x;
        p0.z = base + h.x;  p0.w = h.y;
        p1.x = p0.z + h.y;  p1.y = h.z;
        p1.z = p1.x + h.z;  p1.w = h.w;
        reinterpret_cast<int4*>(&g_UH[i0])[0] = p0;
        reinterpret_cast<int4*>(&g_UH[i0])[1] = p1;
        // self-clean H for the next replay
        *reinterpret_cast<int4*>(g_H + i0) = make_int4(0, 0, 0, 0);
    } else {
        // scan of x tile sums (xnt <= 1024 entries, 4 per thread)
        float v[4];
        #pragma unroll
        for (int k = 0; k < 4; k++) {
            int i = t * 4 + k;
            v[k] = (i < xnt) ? g_xsum[i] : 0.f;
        }
        float ts = ((v[0] + v[1]) + v[2]) + v[3];
        float sc = ts;
        #pragma unroll
        for (int off = 1; off < 32; off <<= 1) {
            float n = __shfl_up_sync(0xffffffffu, sc, off);
            if (lane >= off) sc += n;
        }
        __shared__ float wtf[8], wof[8], sh_total;
        if (lane == 31) wtf[w] = sc;
        __syncthreads();
        if (t < 8) {
            float wv = wtf[t], ws = wv;
            #pragma unroll
            for (int off = 1; off < 8; off <<= 1) {
                float n = __shfl_up_sync(0xffu, ws, off);
                if (t >= off) ws += n;
            }
            wof[t] = ws - wv;
            if (t == 7) sh_total = ws;
        }
        __syncthreads();
        if (t == 0) g_inv_total = 1.0f / sh_total;
        float acc = (sc - ts) + wof[w];
        #pragma unroll
        for (int k = 0; k < 4; k++) {
            int i = t * 4 + k;
            if (i < xnt) g_xoff[i] = acc;
            acc += v[k];
        }
    }
}

// ---- L3: per-block hsum scan (smem) + x scan + gather + finalize ----
__global__ void k_gather(const float* __restrict__ x, float* __restrict__ out,
                         int N, int M, int xnt) {
    int t = threadIdx.x, lane = t & 31, w = t >> 5;
    __shared__ int sh_hoff[HT];                      // 4KB: global U tile offsets

    // stage A: block-scan the 1024 H-tile totals (redundant per block, hidden)
    {
        int4 hs = reinterpret_cast<const int4*>(g_hsum)[t];
        int s = hs.x + hs.y + hs.z + hs.w;
        int sc = s;
        #pragma unroll
        for (int off = 1; off < 32; off <<= 1) {
            int n = __shfl_up_sync(0xffffffffu, sc, off);
            if (lane >= off) sc += n;
        }
        __shared__ int wt[8], wo[8];
        if (lane == 31) wt[w] = sc;
        __syncthreads();
        if (t < 8) {
            int wv = wt[t], ws = wv;
            #pragma unroll
            for (int off = 1; off < 8; off <<= 1) {
                int n = __shfl_up_sync(0xffu, ws, off);
                if (t >= off) ws += n;
            }
            wo[t] = ws - wv;
        }
        __syncthreads();
        int base = (sc - s) + wo[w];
        sh_hoff[t * 4 + 0] = base;
        sh_hoff[t * 4 + 1] = base + hs.x;
        sh_hoff[t * 4 + 2] = base + hs.x + hs.y;
        sh_hoff[t * 4 + 3] = base + hs.x + hs.y + hs.z;
    }
    __syncthreads();

    // stage B: x scan within this tile, then gather + accumulate
    int tile = blockIdx.x;
    int i0 = tile * TILE + t * 4;
    float v[4];
    bool full = (i0 + 3 < N);
    if (full) {
        float4 f = *reinterpret_cast<const float4*>(x + i0);
        v[0] = f.x; v[1] = f.y; v[2] = f.z; v[3] = f.w;
    } else {
        #pragma unroll
        for (int k = 0; k < 4; k++) v[k] = (i0 + k < N) ? x[i0 + k] : 0.f;
    }
    float s = ((v[0] + v[1]) + v[2]) + v[3];
    float sc = s;
    #pragma unroll
    for (int off = 1; off < 32; off <<= 1) {
        float n = __shfl_up_sync(0xffffffffu, sc, off);
        if (lane >= off) sc += n;
    }
    __shared__ float wtf[8], wof[8];
    if (lane == 31) wtf[w] = sc;
    __syncthreads();
    if (t < 8) {
        float wv = wtf[t], ws = wv;
        #pragma unroll
        for (int off = 1; off < 8; off <<= 1) {
            float n = __shfl_up_sync(0xffu, ws, off);
            if (t >= off) ws += n;
        }
        wof[t] = ws - wv;
    }
    __syncthreads();
    float acc = g_xoff[tile] + (sc - s) + wof[w];
    float inv = g_inv_total;

    long long local = 0;
    #pragma unroll
    for (int e = 0; e < 4; e++) {
        int i = i0 + e;
        acc += v[e];
        if (i < N && i != N - 1) {                   // skip last term == clip to N-1
            float ck = (acc * inv) * (float)KTAB;
            int k = (int)ck;
            if (k > KTAB - 1) k = KTAB - 1;
            if (k < 0) k = 0;
            float frac = ck - (float)k;
            if (frac < 0.f) frac = 0.f;
            if (frac > 1.f) frac = 1.f;
            int2 uh = __ldg(&g_UH[k]);
            int U = sh_hoff[k >> 10] + uh.x;         // global exclusive prefix
            long long ip = ((long long)(M - U)) << 16;
            int q = (int)(frac * (float)uh.y * 65536.0f);
            local += ip - (long long)q;
        }
    }
    #pragma unroll
    for (int off = 16; off; off >>= 1)
        local += __shfl_down_sync(0xffffffffu, local, off);
    __shared__ long long ws8[8];
    if (lane == 0) ws8[w] = local;
    __syncthreads();
    if (t < 8) {
        long long vv = ws8[t];
        #pragma unroll
        for (int off = 4; off; off >>= 1)
            vv += __shfl_down_sync(0xffu, vv, off);
        if (t == 0) {
            atomicAdd(&g_acc, (unsigned long long)vv);
            __threadfence();
            unsigned d = atomicAdd(&g_xdone, 1u);
            if (d == (unsigned)(gridDim.x - 1)) {    // last block finalizes
                unsigned long long a = atomicAdd(&g_acc, 0ull);
                out[0] = (float)((double)a / (65536.0 * (double)M));
                g_acc = 0ull;                        // replay-safe resets
                g_xdone = 0u;
            }
        }
    }
}

extern "C" void kernel_launch(void* const* d_in, const int* in_sizes, int n_in,
                              void* d_out, int out_size) {
    const float* x = (const float*)d_in[0];
    const float* u = (const float*)d_in[1];
    float* out = (float*)d_out;
    int N = in_sizes[0];
    int M = in_sizes[1];
    int xnt = (N + TILE - 1) / TILE;                 // x tiles (<= 1024)
    int HB  = (M + TILE - 1) / TILE;                 // histogram blocks

    k_pre<<<HB + xnt, 256>>>(u, x, N, M, HB);
    k_mid<<<HT + 1, 256>>>(xnt);
    k_gather<<<xnt, 256>>>(x, out, N, M, xnt);
}

// round 8
// speedup vs baseline: 1.7239x; 1.0100x over previous
#include <cuda_runtime.h>

// MultinomialModule via guide-table interpolation (atomic-free build):
//   T[k] = #{i : cdf[i] < k/K},  K = 2^20   (cdf = cumsum(x)/total, monotone)
//   idx(u) ~= T[b] + frac * (T[b+1]-T[b]),  b = floor(u*K)  (exact *2^20)
//   out = mean(clip(idx, 0, N-1)); fixed-point 1/65536, int64 accumulate.
// T is built by deterministic range scatter: cdf computed in registers, each
// bin written by exactly one element (boundaries derived from canonical floats:
// tile edges from g_xoff, thread seams from the neighbor's shared c3).
//
//   L1 k_pre     : x tile sums; last block scans them -> g_xoff, 1/total
//   L2 k_scatter : x scan per tile -> registers cdf -> range-scatter T
//   L3 k_u       : per-sample interpolation from T, reduce, finalize

#define TILE   1024
#define NT_MAX 1024
#define KBITS  20
#define KTAB   (1 << KBITS)

__device__ int   g_T[KTAB + 2];
__device__ float g_xsum[NT_MAX];
__device__ float g_xoff[NT_MAX + 1];   // exclusive offsets; [xnt] = total
__device__ float g_inv_total;
__device__ unsigned long long g_acc;   // zero-init; reset by finalize
__device__ unsigned g_done1;           // zero-init; reset after use
__device__ unsigned g_done2;           // zero-init; reset by finalize

// ---- L1: x tile sums, last block scans the tile sums ----
__global__ void k_pre(const float* __restrict__ x, int N, int xnt) {
    int tile = blockIdx.x, t = threadIdx.x;
    int lane = t & 31, w = t >> 5;
    int i0 = tile * TILE + t * 4;
    float s = 0.f;
    if (i0 + 3 < N) {
        float4 v = *reinterpret_cast<const float4*>(x + i0);
        s = ((v.x + v.y) + v.z) + v.w;
    } else {
        #pragma unroll
        for (int k = 0; k < 4; k++) if (i0 + k < N) s += x[i0 + k];
    }
    #pragma unroll
    for (int off = 16; off; off >>= 1) s += __shfl_down_sync(0xffffffffu, s, off);
    __shared__ float wsf[8];
    if (lane == 0) wsf[w] = s;
    __syncthreads();
    if (t < 8) {
        float v = wsf[t];
        #pragma unroll
        for (int off = 4; off; off >>= 1) v += __shfl_down_sync(0xffu, v, off);
        if (t == 0) g_xsum[tile] = v;
    }
    // last finishing block scans all tile sums
    __shared__ int amlast;
    if (t == 0) {
        __threadfence();
        amlast = (atomicAdd(&g_done1, 1u) == (unsigned)(xnt - 1));
    }
    __syncthreads();
    if (!amlast) return;
    __threadfence();                               // acquire prior writes

    float v[4];
    #pragma unroll
    for (int k = 0; k < 4; k++) {
        int i = t * 4 + k;
        v[k] = (i < xnt) ? g_xsum[i] : 0.f;
    }
    float ts = ((v[0] + v[1]) + v[2]) + v[3];
    float sc = ts;
    #pragma unroll
    for (int off = 1; off < 32; off <<= 1) {
        float n = __shfl_up_sync(0xffffffffu, sc, off);
        if (lane >= off) sc += n;
    }
    __shared__ float wtf[8], wof[8], sh_total;
    if (lane == 31) wtf[w] = sc;
    __syncthreads();
    if (t < 8) {
        float wv = wtf[t], ws = wv;
        #pragma unroll
        for (int off = 1; off < 8; off <<= 1) {
            float n = __shfl_up_sync(0xffu, ws, off);
            if (t >= off) ws += n;
        }
        wof[t] = ws - wv;
        if (t == 7) sh_total = ws;
    }
    __syncthreads();
    if (t == 0) { g_inv_total = 1.0f / sh_total; g_done1 = 0u; }
    float acc = (sc - ts) + wof[w];
    #pragma unroll
    for (int k = 0; k < 4; k++) {
        int i = t * 4 + k;
        if (i < xnt) g_xoff[i] = acc;
        acc += v[k];
        if (i == xnt - 1) g_xoff[xnt] = acc;       // total (canonical end)
    }
}

// ceil of c*K as clamped int bin
__device__ __forceinline__ int binceil(float c, int lo, int hi) {
    int b = (int)ceilf(c * (float)KTAB);
    if (b < lo) b = lo;
    if (b > hi) b = hi;
    return b;
}

// ---- L2: x scan per tile -> cdf in registers -> deterministic range scatter ----
__global__ void k_scatter(const float* __restrict__ x, int N, int xnt) {
    int tile = blockIdx.x, t = threadIdx.x;
    int lane = t & 31, w = t >> 5;
    int i0 = tile * TILE + t * 4;
    float inv = g_inv_total;

    float v[4];
    if (i0 + 3 < N) {
        float4 f = *reinterpret_cast<const float4*>(x + i0);
        v[0] = f.x; v[1] = f.y; v[2] = f.z; v[3] = f.w;
    } else {
        #pragma unroll
        for (int k = 0; k < 4; k++) v[k] = (i0 + k < N) ? x[i0 + k] : 0.f;
    }
    float s = ((v[0] + v[1]) + v[2]) + v[3];
    float sc = s;
    #pragma unroll
    for (int off = 1; off < 32; off <<= 1) {
        float n = __shfl_up_sync(0xffffffffu, sc, off);
        if (lane >= off) sc += n;
    }
    __shared__ float wtf[8], wof[8];
    if (lane == 31) wtf[w] = sc;
    __syncthreads();
    if (t < 8) {
        float wv = wtf[t], ws = wv;
        #pragma unroll
        for (int off = 1; off < 8; off <<= 1) {
            float n = __shfl_up_sync(0xffu, ws, off);
            if (t >= off) ws += n;
        }
        wof[t] = ws - wv;
    }
    __syncthreads();
    float acc = g_xoff[tile] + (sc - s) + wof[w];
    float c[4];
    #pragma unroll
    for (int k = 0; k < 4; k++) { acc += v[k]; c[k] = acc * inv; }

    // neighbor's last cdf value (bitwise) for exact thread seams
    __shared__ float sh_c3[256];
    sh_c3[t] = c[3];
    __syncthreads();

    // canonical tile bin range [A0, A1)
    int A0 = binceil(g_xoff[tile] * inv, 0, KTAB);
    int A1 = (tile < xnt - 1) ? binceil(g_xoff[tile + 1] * inv, 0, KTAB) : KTAB;
    if (A1 < A0) A1 = A0;

    int prevB = (t == 0) ? A0 : binceil(sh_c3[t - 1], A0, A1);
    #pragma unroll
    for (int e = 0; e < 4; e++) {
        int i = i0 + e;
        if (i >= N) break;
        int bE;
        bool lastOfTile = (i == N - 1) || (t == 255 && e == 3);
        if (lastOfTile) bE = A1;                   // canonical end (no gap/overlap)
        else            bE = binceil(c[e], A0, A1);
        for (int k = prevB; k < bE; k++) g_T[k] = i;
        prevB = bE;
    }
    if (tile == 0 && t == 0) g_T[KTAB] = N;        // top sentinel for b+1
}

// ---- L3: per-sample interpolation + reduce + finalize ----
__global__ void k_u(const float* __restrict__ u, float* __restrict__ out,
                    int N, int M) {
    int t = threadIdx.x, lane = t & 31, w = t >> 5;
    int j0 = (blockIdx.x * blockDim.x + t) * 4;
    const long long cap = ((long long)(N - 1)) << 16;
    long long local = 0;

    float uu[4];
    int cnt = 0;
    if (j0 + 3 < M) {
        float4 f = *reinterpret_cast<const float4*>(u + j0);
        uu[0] = f.x; uu[1] = f.y; uu[2] = f.z; uu[3] = f.w;
        cnt = 4;
    } else {
        for (int k = 0; k < 4; k++) if (j0 + k < M) uu[cnt++] = u[j0 + k];
    }
    #pragma unroll 4
    for (int k = 0; k < cnt; k++) {
        float ck = uu[k] * (float)KTAB;            // exact *2^20
        int b = (int)ck;
        if (b > KTAB - 1) b = KTAB - 1;
        if (b < 0) b = 0;
        float frac = ck - (float)b;
        int Tb = __ldg(&g_T[b]);
        int dT = __ldg(&g_T[b + 1]) - Tb;
        long long e64 = ((long long)Tb << 16)
                      + (long long)(int)(frac * (float)dT * 65536.0f);
        if (e64 > cap) e64 = cap;
        local += e64;
    }
    #pragma unroll
    for (int off = 16; off; off >>= 1)
        local += __shfl_down_sync(0xffffffffu, local, off);
    __shared__ long long ws8[8];
    if (lane == 0) ws8[w] = local;
    __syncthreads();
    if (t < 8) {
        long long vv = ws8[t];
        #pragma unroll
        for (int off = 4; off; off >>= 1)
            vv += __shfl_down_sync(0xffu, vv, off);
        if (t == 0) {
            atomicAdd(&g_acc, (unsigned long long)vv);
            __threadfence();
            unsigned d = atomicAdd(&g_done2, 1u);
            if (d == (unsigned)(gridDim.x - 1)) {
                unsigned long long a = atomicAdd(&g_acc, 0ull);
                out[0] = (float)((double)a / (65536.0 * (double)M));
                g_acc = 0ull;                      // replay-safe resets
                g_done2 = 0u;
            }
        }
    }
}

extern "C" void kernel_launch(void* const* d_in, const int* in_sizes, int n_in,
                              void* d_out, int out_size) {
    const float* x = (const float*)d_in[0];
    const float* u = (const float*)d_in[1];
    float* out = (float*)d_out;
    int N = in_sizes[0];
    int M = in_sizes[1];
    int xnt = (N + TILE - 1) / TILE;

    k_pre<<<xnt, 256>>>(x, N, xnt);
    k_scatter<<<xnt, 256>>>(x, N, xnt);
    k_u<<<((M + 3) / 4 + 255) / 256, 256>>>(u, out, N, M);
}